// round 1
// baseline (speedup 1.0000x reference)
#include <cuda_runtime.h>
#include <cuda_fp16.h>
#include <cstdint>

#define Bn 4
#define Nn 256
#define Cc 32
#define Mm 4
#define OUTn 64

// ---------------- scratch (device globals: no allocation allowed) ----------------
__device__ float g_S1[Bn*Nn*Cc];      // rowsum  (mean over axis1): S1[b,t,c] = (1/n) sum_i x[b,i,t,c]
__device__ float g_S2[Bn*Nn*Cc];      // colsum  (mean over axis2): S2[b,t,c] = (1/n) sum_j x[b,t,j,c]
__device__ float g_D [Bn*Nn*Cc];      // diag:   D[b,t,c] = x[b,t,t,c]
__device__ float g_p [Bn*Nn*Mm];      // sigmoid neighborhood
__device__ float g_U [Bn*Nn*Mm*Cc];   // U[b,t,m,c] = (1/n) sum_i p[i,m] x[b,i,t,c]
__device__ float g_V [Bn*Nn*Mm*Cc];   // V[b,t,m,c] = (1/n) sum_j p[j,m] x[b,t,j,c]
__device__ float g_rcs2[Bn*Mm*Cc];
__device__ float g_ds2 [Bn*Mm*Cc];
__device__ float g_z0 [Bn*OUTn];      // obj0d@w0d + b0d + b1d + b2d
__device__ float g_add[Bn*Nn*OUTn];   // per (b, j, o) additive term
__device__ __half g_Wt[OUTn*2*Mm*Cc]; // w2d transposed: Wt[o][k], k = 0..255

// ---------------- pass 1: row access -> S2, D ----------------
__global__ void k_rowpass(const float* __restrict__ x){
    int bt = blockIdx.x;                // b*Nn + t
    int t = bt & (Nn-1);
    const float* xrow = x + (size_t)bt * Nn * Cc;
    int c = threadIdx.x & 31, g = threadIdx.x >> 5;
    float s = 0.f;
    for (int j = g; j < Nn; j += 8) s += xrow[j*Cc + c];
    __shared__ float red[8][32];
    red[g][c] = s;
    __syncthreads();
    if (g == 0){
        float tot = 0.f;
        #pragma unroll
        for (int k = 0; k < 8; k++) tot += red[k][c];
        g_S2[bt*Cc + c] = tot * (1.0f/Nn);
        g_D [bt*Cc + c] = xrow[t*Cc + c];
    }
}

// ---------------- pass 2: column access -> S1 ----------------
__global__ void k_colpass(const float* __restrict__ x){
    int bt = blockIdx.x;
    int b = bt >> 8, t = bt & (Nn-1);
    const float* xb = x + (size_t)b*Nn*Nn*Cc + (size_t)t*Cc;
    int c = threadIdx.x & 31, g = threadIdx.x >> 5;
    float s = 0.f;
    for (int i = g; i < Nn; i += 8) s += xb[(size_t)i*Nn*Cc + c];
    __shared__ float red[8][32];
    red[g][c] = s;
    __syncthreads();
    if (g == 0){
        float tot = 0.f;
        #pragma unroll
        for (int k = 0; k < 8; k++) tot += red[k][c];
        g_S1[bt*Cc + c] = tot * (1.0f/Nn);
    }
}

// ---------------- neighborhood sigmoid: p[b,t,m] ----------------
__global__ void k_neighb(const float* __restrict__ w1, const float* __restrict__ b1,
                         const float* __restrict__ w0, const float* __restrict__ b0){
    int b = blockIdx.x;
    __shared__ float rcs[Cc], ds[Cc], z0[Mm];
    __shared__ float r1[8][32], r2[8][32];
    int c = threadIdx.x & 31, g = threadIdx.x >> 5;
    float s1 = 0.f, s2 = 0.f;
    for (int t = g; t < Nn; t += 8){
        s1 += g_S1[(b*Nn + t)*Cc + c];
        s2 += g_D [(b*Nn + t)*Cc + c];
    }
    r1[g][c] = s1; r2[g][c] = s2;
    __syncthreads();
    if (threadIdx.x < 32){
        float a = 0.f, d = 0.f;
        #pragma unroll
        for (int k = 0; k < 8; k++){ a += r1[k][c]; d += r2[k][c]; }
        rcs[c] = a * (1.0f/Nn);
        ds[c]  = d * (1.0f/Nn);
    }
    __syncthreads();
    if (threadIdx.x < Mm){
        int m = threadIdx.x;
        float z = b0[m];
        for (int cc = 0; cc < Cc; cc++)
            z += rcs[cc]*w0[cc*Mm + m] + ds[cc]*w0[(Cc+cc)*Mm + m];
        z0[m] = z;
    }
    __syncthreads();
    int t = threadIdx.x;     // 256 threads == Nn
    const float* S1r = &g_S1[(b*Nn + t)*Cc];
    const float* S2r = &g_S2[(b*Nn + t)*Cc];
    const float* Dr  = &g_D [(b*Nn + t)*Cc];
    float node[Mm];
    #pragma unroll
    for (int m = 0; m < Mm; m++) node[m] = b1[m] + z0[m];
    for (int cc = 0; cc < Cc; cc++){
        float a = S1r[cc], bb = S2r[cc], dd = Dr[cc];
        #pragma unroll
        for (int m = 0; m < Mm; m++)
            node[m] += a*w1[cc*Mm+m] + bb*w1[(Cc+cc)*Mm+m] + dd*w1[(2*Cc+cc)*Mm+m];
    }
    #pragma unroll
    for (int m = 0; m < Mm; m++)
        g_p[(b*Nn + t)*Mm + m] = 1.0f / (1.0f + expf(-node[m]));
}

// ---------------- p-weighted contractions ----------------
__global__ void k_vpass(const float* __restrict__ x){
    int bt = blockIdx.x;
    int b = bt >> 8;
    const float* xrow = x + (size_t)bt * Nn * Cc;
    __shared__ float pj[Nn*Mm];
    __shared__ float red[8*Mm*32];
    for (int idx = threadIdx.x; idx < Nn*Mm; idx += 256) pj[idx] = g_p[b*Nn*Mm + idx];
    __syncthreads();
    int c = threadIdx.x & 31, g = threadIdx.x >> 5;
    float acc[Mm] = {0.f,0.f,0.f,0.f};
    for (int j = g; j < Nn; j += 8){
        float v = xrow[j*Cc + c];
        #pragma unroll
        for (int m = 0; m < Mm; m++) acc[m] += v * pj[j*Mm + m];
    }
    #pragma unroll
    for (int m = 0; m < Mm; m++) red[(g*Mm + m)*32 + c] = acc[m];
    __syncthreads();
    if (g < Mm){
        int m = g;
        float s = 0.f;
        #pragma unroll
        for (int k = 0; k < 8; k++) s += red[(k*Mm + m)*32 + c];
        g_V[(bt*Mm + m)*Cc + c] = s * (1.0f/Nn);
    }
}

__global__ void k_upass(const float* __restrict__ x){
    int bt = blockIdx.x;
    int b = bt >> 8, t = bt & (Nn-1);
    const float* xb = x + (size_t)b*Nn*Nn*Cc + (size_t)t*Cc;
    __shared__ float pi[Nn*Mm];
    __shared__ float red[8*Mm*32];
    for (int idx = threadIdx.x; idx < Nn*Mm; idx += 256) pi[idx] = g_p[b*Nn*Mm + idx];
    __syncthreads();
    int c = threadIdx.x & 31, g = threadIdx.x >> 5;
    float acc[Mm] = {0.f,0.f,0.f,0.f};
    for (int i = g; i < Nn; i += 8){
        float v = xb[(size_t)i*Nn*Cc + c];
        #pragma unroll
        for (int m = 0; m < Mm; m++) acc[m] += v * pi[i*Mm + m];
    }
    #pragma unroll
    for (int m = 0; m < Mm; m++) red[(g*Mm + m)*32 + c] = acc[m];
    __syncthreads();
    if (g < Mm){
        int m = g;
        float s = 0.f;
        #pragma unroll
        for (int k = 0; k < 8; k++) s += red[(k*Mm + m)*32 + c];
        g_U[(bt*Mm + m)*Cc + c] = s * (1.0f/Nn);
    }
}

__global__ void k_rcs2(){
    int b = blockIdx.x;
    int mc = threadIdx.x;           // 128 threads
    int m = mc >> 5, c = mc & 31;
    float s1 = 0.f, s2 = 0.f;
    for (int t = 0; t < Nn; t++){
        float pv = g_p[(b*Nn + t)*Mm + m];
        s1 += pv * g_V[((b*Nn + t)*Mm + m)*Cc + c];
        s2 += pv * pv * g_D[(b*Nn + t)*Cc + c];
    }
    g_rcs2[b*Mm*Cc + mc] = s1 * (1.0f/Nn);
    g_ds2 [b*Mm*Cc + mc] = s2 * (1.0f/Nn);
}

__global__ void k_z0d(const float* __restrict__ w0d, const float* __restrict__ b0d,
                      const float* __restrict__ b1d, const float* __restrict__ b2d){
    int b = threadIdx.x >> 6, o = threadIdx.x & 63;   // 256 threads
    float s = b0d[o] + b1d[o] + b2d[o];
    for (int mc = 0; mc < Mm*Cc; mc++)
        s += g_rcs2[b*Mm*Cc + mc]*w0d[mc*OUTn + o] + g_ds2[b*Mm*Cc + mc]*w0d[(Mm*Cc + mc)*OUTn + o];
    g_z0[b*OUTn + o] = s;
}

// add[b,t,o] = obj1d[b,t,:] @ w1d[:,o] + z0[b,o]   (16 t per block to amortize w1d reads)
__global__ void k_add(const float* __restrict__ w1d){
    int b = blockIdx.x >> 4;
    int t0 = (blockIdx.x & 15) * 16;
    __shared__ float o1[16*384];
    int tid = threadIdx.x;
    for (int idx = tid; idx < 16*384; idx += 256){
        int tl = idx / 384, k = idx - tl*384;
        int t = t0 + tl;
        int seg = k >> 7, mc = k & 127;
        int m = mc >> 5, c = mc & 31;
        float pv = g_p[(b*Nn + t)*Mm + m];
        float val;
        if (seg == 0)      val = pv * g_U[((b*Nn + t)*Mm + m)*Cc + c];
        else if (seg == 1) val = pv * g_V[((b*Nn + t)*Mm + m)*Cc + c];
        else               val = pv * pv * g_D[(b*Nn + t)*Cc + c];
        o1[tl*384 + k] = val;
    }
    __syncthreads();
    int tl4 = tid >> 6, o = tid & 63;
    float acc[4] = {0.f,0.f,0.f,0.f};
    for (int k = 0; k < 384; k++){
        float wv = w1d[k*OUTn + o];
        #pragma unroll
        for (int q = 0; q < 4; q++) acc[q] += o1[(tl4*4 + q)*384 + k] * wv;
    }
    float z = g_z0[b*OUTn + o];
    #pragma unroll
    for (int q = 0; q < 4; q++)
        g_add[(b*Nn + t0 + tl4*4 + q)*OUTn + o] = acc[q] + z;
}

// ---------------- w2d -> half, transposed [o][k] ----------------
__global__ void k_wt(const float* __restrict__ w2d){
    int idx = blockIdx.x * 256 + threadIdx.x;   // 16384
    int o = idx >> 8, k = idx & 255;
    g_Wt[idx] = __float2half(w2d[k*OUTn + o]);
}

// ---------------- main fused GEMM ----------------
__device__ __forceinline__ void mma16816(float* c, const uint32_t* a, uint32_t b0, uint32_t b1){
    asm volatile("mma.sync.aligned.m16n8k16.row.col.f32.f16.f16.f32 "
        "{%0,%1,%2,%3}, {%4,%5,%6,%7}, {%8,%9}, {%0,%1,%2,%3};\n"
        : "+f"(c[0]), "+f"(c[1]), "+f"(c[2]), "+f"(c[3])
        : "r"(a[0]), "r"(a[1]), "r"(a[2]), "r"(a[3]), "r"(b0), "r"(b1));
}

#define AS 264   // padded row stride (halves) for A and W tiles
#define SMEM_MAIN (128*AS*2 + 64*AS*2 + 512*4 + 64*4)

__global__ __launch_bounds__(256, 2) void k_main(const float* __restrict__ x, float* __restrict__ out){
    extern __shared__ __align__(16) char smem[];
    __half* Ash  = (__half*)smem;                 // [128][AS]
    __half* Wsh  = Ash + 128*AS;                  // [64][AS]
    float*  sshf = (float*)(Wsh + 64*AS);         // [128][4] s_m factors
    float*  addsh = sshf + 512;                   // [64]

    int blk = blockIdx.x;
    int ib = blk & 1, j = (blk >> 1) & 255, b = blk >> 9;
    int i0 = ib * 128;
    int tid = threadIdx.x;

    if (tid < 128){
        float4 pi = ((const float4*)g_p)[b*Nn + i0 + tid];
        float4 pj = ((const float4*)g_p)[b*Nn + j];
        ((float4*)sshf)[tid] = make_float4(pi.x*pj.x, pi.y*pj.y, pi.z*pj.z, pi.w*pj.w);
    }
    if (tid < 64) addsh[tid] = g_add[(b*Nn + j)*OUTn + tid];
    {
        const half2* Wt2 = (const half2*)g_Wt;
        #pragma unroll
        for (int it = 0; it < 32; it++){
            int idx = tid + it*256;               // < 8192
            int o = idx >> 7, kp = idx & 127;
            *(half2*)&Wsh[o*AS + kp*2] = Wt2[o*128 + kp];
        }
    }
    __syncthreads();

    // build A tile: A[i][m*32+c] = s_m * x[b,i0+i,j,c];  A[i][128+m*32+c] = s_m * x[b,j,i0+i,c]
    {
        size_t base_c = (((size_t)(b*Nn) + i0)*Nn + j)*Cc;
        size_t base_r = (((size_t)(b*Nn) + j)*Nn + i0)*Cc;
        #pragma unroll
        for (int it = 0; it < 8; it++){
            int idx = tid + it*256;               // < 2048
            int i = idx >> 4, cp = idx & 15;
            float2 v = *(const float2*)(x + base_c + (size_t)i*(Nn*Cc) + cp*2);
            float4 s = ((const float4*)sshf)[i];
            __half* arow = Ash + i*AS + cp*2;
            *(half2*)(arow     ) = __floats2half2_rn(s.x*v.x, s.x*v.y);
            *(half2*)(arow + 32) = __floats2half2_rn(s.y*v.x, s.y*v.y);
            *(half2*)(arow + 64) = __floats2half2_rn(s.z*v.x, s.z*v.y);
            *(half2*)(arow + 96) = __floats2half2_rn(s.w*v.x, s.w*v.y);
        }
        #pragma unroll
        for (int it = 0; it < 8; it++){
            int idx = tid + it*256;
            int i = idx >> 4, cp = idx & 15;
            float2 v = *(const float2*)(x + base_r + (size_t)i*Cc + cp*2);
            float4 s = ((const float4*)sshf)[i];
            __half* arow = Ash + i*AS + 128 + cp*2;
            *(half2*)(arow     ) = __floats2half2_rn(s.x*v.x, s.x*v.y);
            *(half2*)(arow + 32) = __floats2half2_rn(s.y*v.x, s.y*v.y);
            *(half2*)(arow + 64) = __floats2half2_rn(s.z*v.x, s.z*v.y);
            *(half2*)(arow + 96) = __floats2half2_rn(s.w*v.x, s.w*v.y);
        }
    }
    __syncthreads();

    int lane = tid & 31, wid = tid >> 5;
    int wr = wid >> 1, wc = wid & 1;              // 4 row-tiles x 2 col-tiles of warps
    int gid = lane >> 2, tg = lane & 3;
    float acc[2][4][4];
    #pragma unroll
    for (int rt = 0; rt < 2; rt++)
        #pragma unroll
        for (int nt = 0; nt < 4; nt++)
            #pragma unroll
            for (int q = 0; q < 4; q++) acc[rt][nt][q] = 0.f;

    #pragma unroll
    for (int kk = 0; kk < 16; kk++){
        int k0 = kk*16;
        uint32_t a[2][4];
        #pragma unroll
        for (int rt = 0; rt < 2; rt++){
            int r = wr*32 + rt*16 + gid;
            const __half* ap = Ash + r*AS + k0 + tg*2;
            a[rt][0] = *(const uint32_t*)(ap);
            a[rt][1] = *(const uint32_t*)(ap + 8*AS);
            a[rt][2] = *(const uint32_t*)(ap + 8);
            a[rt][3] = *(const uint32_t*)(ap + 8*AS + 8);
        }
        #pragma unroll
        for (int nt = 0; nt < 4; nt++){
            int o = wc*32 + nt*8 + gid;
            const __half* bp = Wsh + o*AS + k0 + tg*2;
            uint32_t b0 = *(const uint32_t*)(bp);
            uint32_t b1 = *(const uint32_t*)(bp + 8);
            mma16816(acc[0][nt], a[0], b0, b1);
            mma16816(acc[1][nt], a[1], b0, b1);
        }
    }

    #pragma unroll
    for (int rt = 0; rt < 2; rt++){
        int r = i0 + wr*32 + rt*16 + gid;
        #pragma unroll
        for (int nt = 0; nt < 4; nt++){
            int o = wc*32 + nt*8 + tg*2;
            float2 ad = *(const float2*)&addsh[o];
            size_t base = (((size_t)(b*Nn) + r)*Nn + j)*OUTn + o;
            float2 v0 = make_float2(acc[rt][nt][0] + ad.x, acc[rt][nt][1] + ad.y);
            float2 v1 = make_float2(acc[rt][nt][2] + ad.x, acc[rt][nt][3] + ad.y);
            *(float2*)(out + base) = v0;
            *(float2*)(out + base + (size_t)8*Nn*OUTn) = v1;
        }
    }
}

// ---------------- launch ----------------
extern "C" void kernel_launch(void* const* d_in, const int* in_sizes, int n_in,
                              void* d_out, int out_size) {
    const float* x    = (const float*)d_in[0];
    const float* w1nb = (const float*)d_in[1];
    const float* b1nb = (const float*)d_in[2];
    const float* w0nb = (const float*)d_in[3];
    const float* b0nb = (const float*)d_in[4];
    const float* w2d  = (const float*)d_in[5];
    const float* b2d  = (const float*)d_in[6];
    const float* w1d  = (const float*)d_in[7];
    const float* b1d  = (const float*)d_in[8];
    const float* w0d  = (const float*)d_in[9];
    const float* b0d  = (const float*)d_in[10];
    float* out = (float*)d_out;

    cudaFuncSetAttribute(k_main, cudaFuncAttributeMaxDynamicSharedMemorySize, SMEM_MAIN);

    k_wt<<<64, 256>>>(w2d);
    k_rowpass<<<Bn*Nn, 256>>>(x);
    k_colpass<<<Bn*Nn, 256>>>(x);
    k_neighb<<<Bn, 256>>>(w1nb, b1nb, w0nb, b0nb);
    k_vpass<<<Bn*Nn, 256>>>(x);
    k_upass<<<Bn*Nn, 256>>>(x);
    k_rcs2<<<Bn, 128>>>();
    k_z0d<<<1, 256>>>(w0d, b0d, b1d, b2d);
    k_add<<<Bn*16, 256>>>(w1d);
    k_main<<<Bn*Nn*2, 256, SMEM_MAIN>>>(x, out);
}

// round 3
// speedup vs baseline: 1.3285x; 1.3285x over previous
#include <cuda_runtime.h>
#include <cuda_fp16.h>
#include <cstdint>

#define Bn 4
#define Nn 256
#define Cc 32
#define Mm 4
#define OUTn 64

// ---------------- scratch (device globals: no allocation allowed) ----------------
__device__ float g_S1[Bn*Nn*Cc];      // rowsum  (mean over axis1): S1[b,t,c] = (1/n) sum_i x[b,i,t,c]
__device__ float g_S2[Bn*Nn*Cc];      // colsum  (mean over axis2): S2[b,t,c] = (1/n) sum_j x[b,t,j,c]
__device__ float g_D [Bn*Nn*Cc];      // diag:   D[b,t,c] = x[b,t,t,c]
__device__ float g_p [Bn*Nn*Mm];      // sigmoid neighborhood
__device__ float g_U [Bn*Nn*Mm*Cc];   // U[b,t,m,c] = (1/n) sum_i p[i,m] x[b,i,t,c]
__device__ float g_V [Bn*Nn*Mm*Cc];   // V[b,t,m,c] = (1/n) sum_j p[j,m] x[b,t,j,c]
__device__ float g_z0 [Bn*OUTn];      // obj0d@w0d + b0d + b1d + b2d
__device__ float g_add[Bn*Nn*OUTn];   // per (b, j, o) additive term
__device__ __half g_Wt[OUTn*2*Mm*Cc]; // w2d transposed: Wt[o][k], k = 0..255

// ---------------- sweep 1: rowpass (S2, D) + colpass (S1) + w2d->half, one launch ----------------
__global__ void k_sweep1(const float* __restrict__ x, const float* __restrict__ w2d){
    int blk = blockIdx.x;
    int tid = threadIdx.x;
    if (blk >= 2*Bn*Nn){
        // w2d transpose -> half
        int idx = (blk - 2*Bn*Nn) * 256 + tid;   // 16384
        int o = idx >> 8, k = idx & 255;
        g_Wt[idx] = __float2half(w2d[k*OUTn + o]);
        return;
    }
    __shared__ float red[8][32];
    int c = tid & 31, g = tid >> 5;
    if (blk < Bn*Nn){
        // rowpass
        int bt = blk;
        int t = bt & (Nn-1);
        const float* xrow = x + (size_t)bt * Nn * Cc;
        float s = 0.f;
        for (int j = g; j < Nn; j += 8) s += xrow[j*Cc + c];
        red[g][c] = s;
        __syncthreads();
        if (g == 0){
            float tot = 0.f;
            #pragma unroll
            for (int k = 0; k < 8; k++) tot += red[k][c];
            g_S2[bt*Cc + c] = tot * (1.0f/Nn);
            g_D [bt*Cc + c] = xrow[t*Cc + c];
        }
    } else {
        // colpass
        int bt = blk - Bn*Nn;
        int b = bt >> 8, t = bt & (Nn-1);
        const float* xb = x + (size_t)b*Nn*Nn*Cc + (size_t)t*Cc;
        float s = 0.f;
        for (int i = g; i < Nn; i += 8) s += xb[(size_t)i*Nn*Cc + c];
        red[g][c] = s;
        __syncthreads();
        if (g == 0){
            float tot = 0.f;
            #pragma unroll
            for (int k = 0; k < 8; k++) tot += red[k][c];
            g_S1[bt*Cc + c] = tot * (1.0f/Nn);
        }
    }
}

// ---------------- neighborhood sigmoid: p[b,t,m] (weights staged in smem) ----------------
__global__ void k_neighb(const float* __restrict__ w1, const float* __restrict__ b1,
                         const float* __restrict__ w0, const float* __restrict__ b0){
    int b = blockIdx.x;
    __shared__ float w1s[3*Cc*Mm];   // 384
    __shared__ float w0s[2*Cc*Mm];   // 256
    __shared__ float rcs[Cc], ds[Cc], z0[Mm];
    __shared__ float r1[8][32], r2[8][32];
    int tid = threadIdx.x;
    for (int idx = tid; idx < 3*Cc*Mm; idx += 256) w1s[idx] = w1[idx];   // FIX: 384 > 256
    if (tid < 2*Cc*Mm) w0s[tid] = w0[tid];
    int c = tid & 31, g = tid >> 5;
    float s1 = 0.f, s2 = 0.f;
    for (int t = g; t < Nn; t += 8){
        s1 += g_S1[(b*Nn + t)*Cc + c];
        s2 += g_D [(b*Nn + t)*Cc + c];
    }
    r1[g][c] = s1; r2[g][c] = s2;
    __syncthreads();
    if (tid < 32){
        float a = 0.f, d = 0.f;
        #pragma unroll
        for (int k = 0; k < 8; k++){ a += r1[k][c]; d += r2[k][c]; }
        rcs[c] = a * (1.0f/Nn);
        ds[c]  = d * (1.0f/Nn);
    }
    __syncthreads();
    if (tid < Mm){
        int m = tid;
        float z = b0[m];
        #pragma unroll
        for (int cc = 0; cc < Cc; cc++)
            z += rcs[cc]*w0s[cc*Mm + m] + ds[cc]*w0s[(Cc+cc)*Mm + m];
        z0[m] = z;
    }
    __syncthreads();
    int t = tid;     // 256 threads == Nn
    const float* S1r = &g_S1[(b*Nn + t)*Cc];
    const float* S2r = &g_S2[(b*Nn + t)*Cc];
    const float* Dr  = &g_D [(b*Nn + t)*Cc];
    float node[Mm];
    #pragma unroll
    for (int m = 0; m < Mm; m++) node[m] = b1[m] + z0[m];
    #pragma unroll
    for (int cc = 0; cc < Cc; cc++){
        float a = S1r[cc], bb = S2r[cc], dd = Dr[cc];
        #pragma unroll
        for (int m = 0; m < Mm; m++)
            node[m] += a*w1s[cc*Mm+m] + bb*w1s[(Cc+cc)*Mm+m] + dd*w1s[(2*Cc+cc)*Mm+m];
    }
    #pragma unroll
    for (int m = 0; m < Mm; m++)
        g_p[(b*Nn + t)*Mm + m] = 1.0f / (1.0f + expf(-node[m]));
}

// ---------------- sweep 2: p-weighted contractions (V and U) in one launch ----------------
__global__ void k_sweep2(const float* __restrict__ x){
    int blk = blockIdx.x;
    bool is_v = blk < Bn*Nn;
    int bt = is_v ? blk : blk - Bn*Nn;
    int b = bt >> 8, t = bt & (Nn-1);
    const float* base;
    size_t stride;
    if (is_v){ base = x + (size_t)bt * Nn * Cc;                     stride = Cc; }
    else     { base = x + (size_t)b*Nn*Nn*Cc + (size_t)t*Cc;        stride = (size_t)Nn*Cc; }
    __shared__ float pv[Nn*Mm];
    __shared__ float red[8*Mm*32];
    int tid = threadIdx.x;
    for (int idx = tid; idx < Nn*Mm; idx += 256) pv[idx] = g_p[b*Nn*Mm + idx];
    __syncthreads();
    int c = tid & 31, g = tid >> 5;
    float acc[Mm] = {0.f,0.f,0.f,0.f};
    for (int j = g; j < Nn; j += 8){
        float v = base[(size_t)j*stride + c];
        #pragma unroll
        for (int m = 0; m < Mm; m++) acc[m] += v * pv[j*Mm + m];
    }
    #pragma unroll
    for (int m = 0; m < Mm; m++) red[(g*Mm + m)*32 + c] = acc[m];
    __syncthreads();
    if (g < Mm){
        int m = g;
        float s = 0.f;
        #pragma unroll
        for (int k = 0; k < 8; k++) s += red[(k*Mm + m)*32 + c];
        float* dst = is_v ? g_V : g_U;
        dst[(bt*Mm + m)*Cc + c] = s * (1.0f/Nn);
    }
}

// ---------------- fused rcs2/ds2 + z0 (per-batch block, parallel reductions) ----------------
__global__ void k_rcs2z0(const float* __restrict__ w0d, const float* __restrict__ b0d,
                         const float* __restrict__ b1d, const float* __restrict__ b2d){
    int b = blockIdx.x;
    __shared__ float rsh[128], dsh[128];
    __shared__ float p1[256], p2[256];
    int tid = threadIdx.x;
    int mc = tid & 127, half = tid >> 7;
    int m = mc >> 5, c = mc & 31;
    float s1 = 0.f, s2 = 0.f;
    int t0 = half*128;
    #pragma unroll 4
    for (int t = t0; t < t0+128; t++){
        float pvv = g_p[(b*Nn + t)*Mm + m];
        s1 += pvv * g_V[((b*Nn + t)*Mm + m)*Cc + c];
        s2 += pvv * pvv * g_D[(b*Nn + t)*Cc + c];
    }
    p1[tid] = s1; p2[tid] = s2;
    __syncthreads();
    if (tid < 128){
        rsh[tid] = (p1[tid] + p1[tid+128]) * (1.0f/Nn);
        dsh[tid] = (p2[tid] + p2[tid+128]) * (1.0f/Nn);
    }
    __syncthreads();
    int o = tid & 63, q = tid >> 6;
    float s = 0.f;
    int k0 = q*32;
    #pragma unroll
    for (int k = k0; k < k0+32; k++)
        s += rsh[k]*w0d[k*OUTn + o] + dsh[k]*w0d[(128+k)*OUTn + o];
    __syncthreads();
    p1[tid] = s;
    __syncthreads();
    if (tid < 64)
        g_z0[b*OUTn + tid] = p1[tid] + p1[tid+64] + p1[tid+128] + p1[tid+192]
                           + b0d[tid] + b1d[tid] + b2d[tid];
}

// add[b,t,o] = obj1d[b,t,:] @ w1d[:,o] + z0[b,o]; w1d staged through smem chunks
#define ADD_SMEM (16*384*4 + 192*64*4)
__global__ void k_add(const float* __restrict__ w1d){
    extern __shared__ float ash[];
    float* o1  = ash;            // [16][384]
    float* wsh = ash + 16*384;   // [192][64]
    int b = blockIdx.x >> 4;
    int t0 = (blockIdx.x & 15) * 16;
    int tid = threadIdx.x;
    for (int idx = tid; idx < 16*384; idx += 256){
        int tl = idx / 384, k = idx - tl*384;
        int t = t0 + tl;
        int seg = k >> 7, mc = k & 127;
        int m = mc >> 5, c = mc & 31;
        float pv = g_p[(b*Nn + t)*Mm + m];
        float val;
        if (seg == 0)      val = pv * g_U[((b*Nn + t)*Mm + m)*Cc + c];
        else if (seg == 1) val = pv * g_V[((b*Nn + t)*Mm + m)*Cc + c];
        else               val = pv * pv * g_D[(b*Nn + t)*Cc + c];
        o1[tl*384 + k] = val;
    }
    int tl4 = tid >> 6, o = tid & 63;
    float acc[4] = {0.f,0.f,0.f,0.f};
    #pragma unroll
    for (int chunk = 0; chunk < 2; chunk++){
        __syncthreads();
        for (int idx = tid; idx < 192*64; idx += 256) wsh[idx] = w1d[chunk*192*64 + idx];
        __syncthreads();
        #pragma unroll 8
        for (int k = 0; k < 192; k++){
            float wv = wsh[k*64 + o];
            #pragma unroll
            for (int q = 0; q < 4; q++)
                acc[q] += o1[(tl4*4 + q)*384 + chunk*192 + k] * wv;
        }
    }
    float z = g_z0[b*OUTn + o];
    #pragma unroll
    for (int q = 0; q < 4; q++)
        g_add[(b*Nn + t0 + tl4*4 + q)*OUTn + o] = acc[q] + z;
}

// ---------------- main fused GEMM ----------------
__device__ __forceinline__ void mma16816(float* c, const uint32_t* a, uint32_t b0, uint32_t b1){
    asm volatile("mma.sync.aligned.m16n8k16.row.col.f32.f16.f16.f32 "
        "{%0,%1,%2,%3}, {%4,%5,%6,%7}, {%8,%9}, {%0,%1,%2,%3};\n"
        : "+f"(c[0]), "+f"(c[1]), "+f"(c[2]), "+f"(c[3])
        : "r"(a[0]), "r"(a[1]), "r"(a[2]), "r"(a[3]), "r"(b0), "r"(b1));
}

#define AS 264   // padded row stride (halves) for A and W tiles
#define SMEM_MAIN (128*AS*2 + 64*AS*2 + 512*4 + 64*4)

__global__ __launch_bounds__(256, 2) void k_main(const float* __restrict__ x, float* __restrict__ out){
    extern __shared__ __align__(16) char smem[];
    __half* Ash  = (__half*)smem;                 // [128][AS]
    __half* Wsh  = Ash + 128*AS;                  // [64][AS]
    float*  sshf = (float*)(Wsh + 64*AS);         // [128][4] s_m factors
    float*  addsh = sshf + 512;                   // [64]

    int blk = blockIdx.x;
    int ib = blk & 1, j = (blk >> 1) & 255, b = blk >> 9;
    int i0 = ib * 128;
    int tid = threadIdx.x;

    if (tid < 128){
        float4 pi = ((const float4*)g_p)[b*Nn + i0 + tid];
        float4 pj = ((const float4*)g_p)[b*Nn + j];
        ((float4*)sshf)[tid] = make_float4(pi.x*pj.x, pi.y*pj.y, pi.z*pj.z, pi.w*pj.w);
    }
    if (tid < 64) addsh[tid] = g_add[(b*Nn + j)*OUTn + tid];
    {
        const half2* Wt2 = (const half2*)g_Wt;
        #pragma unroll
        for (int it = 0; it < 32; it++){
            int idx = tid + it*256;               // < 8192
            int o = idx >> 7, kp = idx & 127;
            *(half2*)&Wsh[o*AS + kp*2] = Wt2[o*128 + kp];
        }
    }
    __syncthreads();

    // build A tile: A[i][m*32+c] = s_m * x[b,i0+i,j,c];  A[i][128+m*32+c] = s_m * x[b,j,i0+i,c]
    {
        size_t base_c = (((size_t)(b*Nn) + i0)*Nn + j)*Cc;
        size_t base_r = (((size_t)(b*Nn) + j)*Nn + i0)*Cc;
        #pragma unroll
        for (int it = 0; it < 8; it++){
            int idx = tid + it*256;               // < 2048
            int i = idx >> 4, cp = idx & 15;
            float2 v = *(const float2*)(x + base_c + (size_t)i*(Nn*Cc) + cp*2);
            float4 s = ((const float4*)sshf)[i];
            __half* arow = Ash + i*AS + cp*2;
            *(half2*)(arow     ) = __floats2half2_rn(s.x*v.x, s.x*v.y);
            *(half2*)(arow + 32) = __floats2half2_rn(s.y*v.x, s.y*v.y);
            *(half2*)(arow + 64) = __floats2half2_rn(s.z*v.x, s.z*v.y);
            *(half2*)(arow + 96) = __floats2half2_rn(s.w*v.x, s.w*v.y);
        }
        #pragma unroll
        for (int it = 0; it < 8; it++){
            int idx = tid + it*256;
            int i = idx >> 4, cp = idx & 15;
            float2 v = *(const float2*)(x + base_r + (size_t)i*Cc + cp*2);
            float4 s = ((const float4*)sshf)[i];
            __half* arow = Ash + i*AS + 128 + cp*2;
            *(half2*)(arow     ) = __floats2half2_rn(s.x*v.x, s.x*v.y);
            *(half2*)(arow + 32) = __floats2half2_rn(s.y*v.x, s.y*v.y);
            *(half2*)(arow + 64) = __floats2half2_rn(s.z*v.x, s.z*v.y);
            *(half2*)(arow + 96) = __floats2half2_rn(s.w*v.x, s.w*v.y);
        }
    }
    __syncthreads();

    int lane = tid & 31, wid = tid >> 5;
    int wr = wid >> 1, wc = wid & 1;              // 4 row-tiles x 2 col-tiles of warps
    int gid = lane >> 2, tg = lane & 3;
    float acc[2][4][4];
    #pragma unroll
    for (int rt = 0; rt < 2; rt++)
        #pragma unroll
        for (int nt = 0; nt < 4; nt++)
            #pragma unroll
            for (int q = 0; q < 4; q++) acc[rt][nt][q] = 0.f;

    #pragma unroll
    for (int kk = 0; kk < 16; kk++){
        int k0 = kk*16;
        uint32_t a[2][4];
        #pragma unroll
        for (int rt = 0; rt < 2; rt++){
            int r = wr*32 + rt*16 + gid;
            const __half* ap = Ash + r*AS + k0 + tg*2;
            a[rt][0] = *(const uint32_t*)(ap);
            a[rt][1] = *(const uint32_t*)(ap + 8*AS);
            a[rt][2] = *(const uint32_t*)(ap + 8);
            a[rt][3] = *(const uint32_t*)(ap + 8*AS + 8);
        }
        #pragma unroll
        for (int nt = 0; nt < 4; nt++){
            int o = wc*32 + nt*8 + gid;
            const __half* bp = Wsh + o*AS + k0 + tg*2;
            uint32_t b0 = *(const uint32_t*)(bp);
            uint32_t b1 = *(const uint32_t*)(bp + 8);
            mma16816(acc[0][nt], a[0], b0, b1);
            mma16816(acc[1][nt], a[1], b0, b1);
        }
    }

    #pragma unroll
    for (int rt = 0; rt < 2; rt++){
        int r = i0 + wr*32 + rt*16 + gid;
        #pragma unroll
        for (int nt = 0; nt < 4; nt++){
            int o = wc*32 + nt*8 + tg*2;
            float2 ad = *(const float2*)&addsh[o];
            size_t base = (((size_t)(b*Nn) + r)*Nn + j)*OUTn + o;
            float2 v0 = make_float2(acc[rt][nt][0] + ad.x, acc[rt][nt][1] + ad.y);
            float2 v1 = make_float2(acc[rt][nt][2] + ad.x, acc[rt][nt][3] + ad.y);
            *(float2*)(out + base) = v0;
            *(float2*)(out + base + (size_t)8*Nn*OUTn) = v1;
        }
    }
}

// ---------------- launch ----------------
extern "C" void kernel_launch(void* const* d_in, const int* in_sizes, int n_in,
                              void* d_out, int out_size) {
    const float* x    = (const float*)d_in[0];
    const float* w1nb = (const float*)d_in[1];
    const float* b1nb = (const float*)d_in[2];
    const float* w0nb = (const float*)d_in[3];
    const float* b0nb = (const float*)d_in[4];
    const float* w2d  = (const float*)d_in[5];
    const float* b2d  = (const float*)d_in[6];
    const float* w1d  = (const float*)d_in[7];
    const float* b1d  = (const float*)d_in[8];
    const float* w0d  = (const float*)d_in[9];
    const float* b0d  = (const float*)d_in[10];
    float* out = (float*)d_out;

    cudaFuncSetAttribute(k_main, cudaFuncAttributeMaxDynamicSharedMemorySize, SMEM_MAIN);
    cudaFuncSetAttribute(k_add, cudaFuncAttributeMaxDynamicSharedMemorySize, ADD_SMEM);

    k_sweep1<<<2*Bn*Nn + 64, 256>>>(x, w2d);
    k_neighb<<<Bn, 256>>>(w1nb, b1nb, w0nb, b0nb);
    k_sweep2<<<2*Bn*Nn, 256>>>(x);
    k_rcs2z0<<<Bn, 256>>>(w0d, b0d, b1d, b2d);
    k_add<<<Bn*16, 256, ADD_SMEM>>>(w1d);
    k_main<<<Bn*Nn*2, 256, SMEM_MAIN>>>(x, out);
}

// round 5
// speedup vs baseline: 1.4344x; 1.0797x over previous
#include <cuda_runtime.h>
#include <cuda_fp16.h>
#include <cstdint>

#define Bn 4
#define Nn 256
#define Cc 32
#define Mm 4
#define OUTn 64

// ---------------- scratch (device globals: no allocation allowed) ----------------
__device__ float g_S1[Bn*Nn*Cc];      // rowsum  (mean over axis1): S1[b,t,c] = (1/n) sum_i x[b,i,t,c]
__device__ float g_S2[Bn*Nn*Cc];      // colsum  (mean over axis2): S2[b,t,c] = (1/n) sum_j x[b,t,j,c]
__device__ float g_D [Bn*Nn*Cc];      // diag:   D[b,t,c] = x[b,t,t,c]
__device__ float g_p [Bn*Nn*Mm];      // sigmoid neighborhood
__device__ float g_U [Bn*Nn*Mm*Cc];   // U[b,t,m,c] = (1/n) sum_i p[i,m] x[b,i,t,c]
__device__ float g_V [Bn*Nn*Mm*Cc];   // V[b,t,m,c] = (1/n) sum_j p[j,m] x[b,t,j,c]
__device__ float g_z0 [Bn*OUTn];      // obj0d@w0d + b0d + b1d + b2d
__device__ float g_add[Bn*Nn*OUTn];   // per (b, j, o) additive term
__device__ __half g_Wt[OUTn*2*Mm*Cc]; // w2d transposed: Wt[o][k], k = 0..255

// ---------------- sweep 1: rowpass (S2, D) + colpass (S1) + w2d->half, one launch ----------------
__global__ void k_sweep1(const float* __restrict__ x, const float* __restrict__ w2d){
    int blk = blockIdx.x;
    int tid = threadIdx.x;
    if (blk >= 2*Bn*Nn){
        // w2d transpose -> half
        int idx = (blk - 2*Bn*Nn) * 256 + tid;   // 16384
        int o = idx >> 8, k = idx & 255;
        g_Wt[idx] = __float2half(w2d[k*OUTn + o]);
        return;
    }
    __shared__ float red[8][32];
    int c = tid & 31, g = tid >> 5;
    if (blk < Bn*Nn){
        // rowpass
        int bt = blk;
        int t = bt & (Nn-1);
        const float* xrow = x + (size_t)bt * Nn * Cc;
        float s = 0.f;
        for (int j = g; j < Nn; j += 8) s += xrow[j*Cc + c];
        red[g][c] = s;
        __syncthreads();
        if (g == 0){
            float tot = 0.f;
            #pragma unroll
            for (int k = 0; k < 8; k++) tot += red[k][c];
            g_S2[bt*Cc + c] = tot * (1.0f/Nn);
            g_D [bt*Cc + c] = xrow[t*Cc + c];
        }
    } else {
        // colpass
        int bt = blk - Bn*Nn;
        int b = bt >> 8, t = bt & (Nn-1);
        const float* xb = x + (size_t)b*Nn*Nn*Cc + (size_t)t*Cc;
        float s = 0.f;
        for (int i = g; i < Nn; i += 8) s += xb[(size_t)i*Nn*Cc + c];
        red[g][c] = s;
        __syncthreads();
        if (g == 0){
            float tot = 0.f;
            #pragma unroll
            for (int k = 0; k < 8; k++) tot += red[k][c];
            g_S1[bt*Cc + c] = tot * (1.0f/Nn);
        }
    }
}

// ---------------- neighborhood sigmoid: p[b,t,m] (weights staged in smem) ----------------
__global__ void k_neighb(const float* __restrict__ w1, const float* __restrict__ b1,
                         const float* __restrict__ w0, const float* __restrict__ b0){
    int b = blockIdx.x;
    __shared__ float w1s[3*Cc*Mm];   // 384
    __shared__ float w0s[2*Cc*Mm];   // 256
    __shared__ float rcs[Cc], ds[Cc], z0[Mm];
    __shared__ float r1[8][32], r2[8][32];
    int tid = threadIdx.x;
    for (int idx = tid; idx < 3*Cc*Mm; idx += 256) w1s[idx] = w1[idx];
    if (tid < 2*Cc*Mm) w0s[tid] = w0[tid];
    int c = tid & 31, g = tid >> 5;
    float s1 = 0.f, s2 = 0.f;
    for (int t = g; t < Nn; t += 8){
        s1 += g_S1[(b*Nn + t)*Cc + c];
        s2 += g_D [(b*Nn + t)*Cc + c];
    }
    r1[g][c] = s1; r2[g][c] = s2;
    __syncthreads();
    if (tid < 32){
        float a = 0.f, d = 0.f;
        #pragma unroll
        for (int k = 0; k < 8; k++){ a += r1[k][c]; d += r2[k][c]; }
        rcs[c] = a * (1.0f/Nn);
        ds[c]  = d * (1.0f/Nn);
    }
    __syncthreads();
    if (tid < Mm){
        int m = tid;
        float z = b0[m];
        #pragma unroll
        for (int cc = 0; cc < Cc; cc++)
            z += rcs[cc]*w0s[cc*Mm + m] + ds[cc]*w0s[(Cc+cc)*Mm + m];
        z0[m] = z;
    }
    __syncthreads();
    int t = tid;     // 256 threads == Nn
    const float* S1r = &g_S1[(b*Nn + t)*Cc];
    const float* S2r = &g_S2[(b*Nn + t)*Cc];
    const float* Dr  = &g_D [(b*Nn + t)*Cc];
    float node[Mm];
    #pragma unroll
    for (int m = 0; m < Mm; m++) node[m] = b1[m] + z0[m];
    #pragma unroll
    for (int cc = 0; cc < Cc; cc++){
        float a = S1r[cc], bb = S2r[cc], dd = Dr[cc];
        #pragma unroll
        for (int m = 0; m < Mm; m++)
            node[m] += a*w1s[cc*Mm+m] + bb*w1s[(Cc+cc)*Mm+m] + dd*w1s[(2*Cc+cc)*Mm+m];
    }
    #pragma unroll
    for (int m = 0; m < Mm; m++)
        g_p[(b*Nn + t)*Mm + m] = 1.0f / (1.0f + expf(-node[m]));
}

// ---------------- sweep 2: p-weighted contractions (V and U) in one launch ----------------
__global__ void k_sweep2(const float* __restrict__ x){
    int blk = blockIdx.x;
    bool is_v = blk < Bn*Nn;
    int bt = is_v ? blk : blk - Bn*Nn;
    int b = bt >> 8, t = bt & (Nn-1);
    const float* base;
    size_t stride;
    if (is_v){ base = x + (size_t)bt * Nn * Cc;                     stride = Cc; }
    else     { base = x + (size_t)b*Nn*Nn*Cc + (size_t)t*Cc;        stride = (size_t)Nn*Cc; }
    __shared__ float pv[Nn*Mm];
    __shared__ float red[8*Mm*32];
    int tid = threadIdx.x;
    for (int idx = tid; idx < Nn*Mm; idx += 256) pv[idx] = g_p[b*Nn*Mm + idx];
    __syncthreads();
    int c = tid & 31, g = tid >> 5;
    float acc[Mm] = {0.f,0.f,0.f,0.f};
    for (int j = g; j < Nn; j += 8){
        float v = base[(size_t)j*stride + c];
        #pragma unroll
        for (int m = 0; m < Mm; m++) acc[m] += v * pv[j*Mm + m];
    }
    #pragma unroll
    for (int m = 0; m < Mm; m++) red[(g*Mm + m)*32 + c] = acc[m];
    __syncthreads();
    if (g < Mm){
        int m = g;
        float s = 0.f;
        #pragma unroll
        for (int k = 0; k < 8; k++) s += red[(k*Mm + m)*32 + c];
        float* dst = is_v ? g_V : g_U;
        dst[(bt*Mm + m)*Cc + c] = s * (1.0f/Nn);
    }
}

// ---------------- fused rcs2/ds2 + z0: 1024 threads, t-sliced for MLP ----------------
__global__ __launch_bounds__(1024) void k_rcs2z0(const float* __restrict__ w0d, const float* __restrict__ b0d,
                         const float* __restrict__ b1d, const float* __restrict__ b2d){
    int b = blockIdx.x;
    __shared__ float pr1[1024], pr2[1024];
    __shared__ float rsh[128], dsh[128];
    int tid = threadIdx.x;
    int mc = tid & 127, slice = tid >> 7;   // 8 slices of 32 t each
    int m = mc >> 5, c = mc & 31;
    float s1 = 0.f, s2 = 0.f;
    int t0 = slice * 32;
    #pragma unroll 8
    for (int t = t0; t < t0+32; t++){
        float pvv = g_p[(b*Nn + t)*Mm + m];
        s1 += pvv * g_V[((b*Nn + t)*Mm + m)*Cc + c];
        s2 += pvv * pvv * g_D[(b*Nn + t)*Cc + c];
    }
    pr1[tid] = s1; pr2[tid] = s2;
    __syncthreads();
    if (tid < 128){
        float a = 0.f, d = 0.f;
        #pragma unroll
        for (int k = 0; k < 8; k++){ a += pr1[k*128 + tid]; d += pr2[k*128 + tid]; }
        rsh[tid] = a * (1.0f/Nn);
        dsh[tid] = d * (1.0f/Nn);
    }
    __syncthreads();
    // z0[o] = sum_k rsh[k] w0d[k][o] + dsh[k] w0d[128+k][o]  (16-way split over k)
    int o = tid & 63, q = tid >> 6;     // q in 0..15
    float s = 0.f;
    int k0 = q * 8;
    #pragma unroll
    for (int k = k0; k < k0+8; k++)
        s += rsh[k]*w0d[k*OUTn + o] + dsh[k]*w0d[(128+k)*OUTn + o];
    __syncthreads();
    pr1[tid] = s;
    __syncthreads();
    if (tid < 64){
        float z = 0.f;
        #pragma unroll
        for (int k = 0; k < 16; k++) z += pr1[k*64 + tid];
        g_z0[b*OUTn + tid] = z + b0d[tid] + b1d[tid] + b2d[tid];
    }
}

// add[b,t,o] = obj1d[b,t,:] @ w1d[:,o] + z0[b,o]; w1d staged through smem chunks
#define ADD_SMEM (16*384*4 + 192*64*4)
__global__ void k_add(const float* __restrict__ w1d){
    extern __shared__ float ash[];
    float* o1  = ash;            // [16][384]
    float* wsh = ash + 16*384;   // [192][64]
    int b = blockIdx.x >> 4;
    int t0 = (blockIdx.x & 15) * 16;
    int tid = threadIdx.x;
    for (int idx = tid; idx < 16*384; idx += 256){
        int tl = idx / 384, k = idx - tl*384;
        int t = t0 + tl;
        int seg = k >> 7, mc = k & 127;
        int m = mc >> 5, c = mc & 31;
        float pv = g_p[(b*Nn + t)*Mm + m];
        float val;
        if (seg == 0)      val = pv * g_U[((b*Nn + t)*Mm + m)*Cc + c];
        else if (seg == 1) val = pv * g_V[((b*Nn + t)*Mm + m)*Cc + c];
        else               val = pv * pv * g_D[(b*Nn + t)*Cc + c];
        o1[tl*384 + k] = val;
    }
    int tl4 = tid >> 6, o = tid & 63;
    float acc[4] = {0.f,0.f,0.f,0.f};
    #pragma unroll
    for (int chunk = 0; chunk < 2; chunk++){
        __syncthreads();
        for (int idx = tid; idx < 192*64; idx += 256) wsh[idx] = w1d[chunk*192*64 + idx];
        __syncthreads();
        #pragma unroll 8
        for (int k = 0; k < 192; k++){
            float wv = wsh[k*64 + o];
            #pragma unroll
            for (int q = 0; q < 4; q++)
                acc[q] += o1[(tl4*4 + q)*384 + chunk*192 + k] * wv;
        }
    }
    float z = g_z0[b*OUTn + o];
    #pragma unroll
    for (int q = 0; q < 4; q++)
        g_add[(b*Nn + t0 + tl4*4 + q)*OUTn + o] = acc[q] + z;
}

// ---------------- main fused GEMM (2 j per block: W tile reused) ----------------
__device__ __forceinline__ void mma16816(float* c, const uint32_t* a, uint32_t b0, uint32_t b1){
    asm volatile("mma.sync.aligned.m16n8k16.row.col.f32.f16.f16.f32 "
        "{%0,%1,%2,%3}, {%4,%5,%6,%7}, {%8,%9}, {%0,%1,%2,%3};\n"
        : "+f"(c[0]), "+f"(c[1]), "+f"(c[2]), "+f"(c[3])
        : "r"(a[0]), "r"(a[1]), "r"(a[2]), "r"(a[3]), "r"(b0), "r"(b1));
}

#define AS 264   // padded row stride (halves) for A and W tiles
#define SMEM_MAIN (128*AS*2 + 64*AS*2 + 512*4 + 64*4)
#define JPB 2

__global__ __launch_bounds__(256, 2) void k_main(const float* __restrict__ x, float* __restrict__ out){
    extern __shared__ __align__(16) char smem[];
    __half* Ash  = (__half*)smem;                 // [128][AS]
    __half* Wsh  = Ash + 128*AS;                  // [64][AS]
    float*  sshf = (float*)(Wsh + 64*AS);         // [128][4] s_m factors
    float*  addsh = sshf + 512;                   // [64]

    int blk = blockIdx.x;
    int ib = blk & 1, jp = (blk >> 1) & 127, b = blk >> 8;
    int i0 = ib * 128;
    int tid = threadIdx.x;

    // W tile: loaded once, reused for JPB j's.
    // 64 rows x 256 halves = 2048 uint4 (FIX: was 4 iterations = half the tile)
    {
        const uint4* Wt4 = (const uint4*)g_Wt;
        #pragma unroll
        for (int it = 0; it < 8; it++){
            int idx = tid + it*256;               // < 2048
            int o = idx >> 5, kq = idx & 31;      // 32 uint4 per 256-half row
            *(uint4*)&Wsh[o*AS + kq*8] = Wt4[idx];
        }
    }

    float4 pi4;
    if (tid < 128) pi4 = ((const float4*)g_p)[b*Nn + i0 + tid];

    int lane = tid & 31, wid = tid >> 5;
    int wr = wid >> 1, wc = wid & 1;              // 4 row-tiles x 2 col-tiles of warps
    int gid = lane >> 2, tg = lane & 3;

    #pragma unroll
    for (int jj = 0; jj < JPB; jj++){
        int j = jp*JPB + jj;
        if (jj > 0) __syncthreads();              // protect Ash/sshf rewrite

        if (tid < 128){
            float4 pj = ((const float4*)g_p)[b*Nn + j];
            ((float4*)sshf)[tid] = make_float4(pi4.x*pj.x, pi4.y*pj.y, pi4.z*pj.z, pi4.w*pj.w);
        }
        if (tid < 64) addsh[tid] = g_add[(b*Nn + j)*OUTn + tid];
        __syncthreads();

        // build A tile: A[i][m*32+c] = s_m * x[b,i0+i,j,c];  A[i][128+m*32+c] = s_m * x[b,j,i0+i,c]
        {
            size_t base_c = (((size_t)(b*Nn) + i0)*Nn + j)*Cc;
            size_t base_r = (((size_t)(b*Nn) + j)*Nn + i0)*Cc;
            #pragma unroll
            for (int it = 0; it < 8; it++){
                int idx = tid + it*256;               // < 2048
                int i = idx >> 4, cp = idx & 15;
                float2 v = *(const float2*)(x + base_c + (size_t)i*(Nn*Cc) + cp*2);
                float4 s = ((const float4*)sshf)[i];
                __half* arow = Ash + i*AS + cp*2;
                *(half2*)(arow     ) = __floats2half2_rn(s.x*v.x, s.x*v.y);
                *(half2*)(arow + 32) = __floats2half2_rn(s.y*v.x, s.y*v.y);
                *(half2*)(arow + 64) = __floats2half2_rn(s.z*v.x, s.z*v.y);
                *(half2*)(arow + 96) = __floats2half2_rn(s.w*v.x, s.w*v.y);
            }
            #pragma unroll
            for (int it = 0; it < 8; it++){
                int idx = tid + it*256;
                int i = idx >> 4, cp = idx & 15;
                float2 v = *(const float2*)(x + base_r + (size_t)i*Cc + cp*2);
                float4 s = ((const float4*)sshf)[i];
                __half* arow = Ash + i*AS + 128 + cp*2;
                *(half2*)(arow     ) = __floats2half2_rn(s.x*v.x, s.x*v.y);
                *(half2*)(arow + 32) = __floats2half2_rn(s.y*v.x, s.y*v.y);
                *(half2*)(arow + 64) = __floats2half2_rn(s.z*v.x, s.z*v.y);
                *(half2*)(arow + 96) = __floats2half2_rn(s.w*v.x, s.w*v.y);
            }
        }
        __syncthreads();

        float acc[2][4][4];
        #pragma unroll
        for (int rt = 0; rt < 2; rt++)
            #pragma unroll
            for (int nt = 0; nt < 4; nt++)
                #pragma unroll
                for (int q = 0; q < 4; q++) acc[rt][nt][q] = 0.f;

        #pragma unroll
        for (int kk = 0; kk < 16; kk++){
            int k0 = kk*16;
            uint32_t a[2][4];
            #pragma unroll
            for (int rt = 0; rt < 2; rt++){
                int r = wr*32 + rt*16 + gid;
                const __half* ap = Ash + r*AS + k0 + tg*2;
                a[rt][0] = *(const uint32_t*)(ap);
                a[rt][1] = *(const uint32_t*)(ap + 8*AS);
                a[rt][2] = *(const uint32_t*)(ap + 8);
                a[rt][3] = *(const uint32_t*)(ap + 8*AS + 8);
            }
            #pragma unroll
            for (int nt = 0; nt < 4; nt++){
                int o = wc*32 + nt*8 + gid;
                const __half* bp = Wsh + o*AS + k0 + tg*2;
                uint32_t b0 = *(const uint32_t*)(bp);
                uint32_t b1 = *(const uint32_t*)(bp + 8);
                mma16816(acc[0][nt], a[0], b0, b1);
                mma16816(acc[1][nt], a[1], b0, b1);
            }
        }

        #pragma unroll
        for (int rt = 0; rt < 2; rt++){
            int r = i0 + wr*32 + rt*16 + gid;
            #pragma unroll
            for (int nt = 0; nt < 4; nt++){
                int o = wc*32 + nt*8 + tg*2;
                float2 ad = *(const float2*)&addsh[o];
                size_t base = (((size_t)(b*Nn) + r)*Nn + j)*OUTn + o;
                float2 v0 = make_float2(acc[rt][nt][0] + ad.x, acc[rt][nt][1] + ad.y);
                float2 v1 = make_float2(acc[rt][nt][2] + ad.x, acc[rt][nt][3] + ad.y);
                *(float2*)(out + base) = v0;
                *(float2*)(out + base + (size_t)8*Nn*OUTn) = v1;
            }
        }
    }
}

// ---------------- launch ----------------
extern "C" void kernel_launch(void* const* d_in, const int* in_sizes, int n_in,
                              void* d_out, int out_size) {
    const float* x    = (const float*)d_in[0];
    const float* w1nb = (const float*)d_in[1];
    const float* b1nb = (const float*)d_in[2];
    const float* w0nb = (const float*)d_in[3];
    const float* b0nb = (const float*)d_in[4];
    const float* w2d  = (const float*)d_in[5];
    const float* b2d  = (const float*)d_in[6];
    const float* w1d  = (const float*)d_in[7];
    const float* b1d  = (const float*)d_in[8];
    const float* w0d  = (const float*)d_in[9];
    const float* b0d  = (const float*)d_in[10];
    float* out = (float*)d_out;

    cudaFuncSetAttribute(k_main, cudaFuncAttributeMaxDynamicSharedMemorySize, SMEM_MAIN);
    cudaFuncSetAttribute(k_add, cudaFuncAttributeMaxDynamicSharedMemorySize, ADD_SMEM);

    k_sweep1<<<2*Bn*Nn + 64, 256>>>(x, w2d);
    k_neighb<<<Bn, 256>>>(w1nb, b1nb, w0nb, b0nb);
    k_sweep2<<<2*Bn*Nn, 256>>>(x);
    k_rcs2z0<<<Bn, 1024>>>(w0d, b0d, b1d, b2d);
    k_add<<<Bn*16, 256, ADD_SMEM>>>(w1d);
    k_main<<<Bn*Nn*2/JPB, 256, SMEM_MAIN>>>(x, out);
}

// round 6
// speedup vs baseline: 1.5958x; 1.1125x over previous
#include <cuda_runtime.h>
#include <cuda_fp16.h>
#include <cstdint>

#define Bn 4
#define Nn 256
#define Cc 32
#define Mm 4
#define OUTn 64

// ---------------- scratch (device globals: no allocation allowed) ----------------
__device__ float g_S1[Bn*Nn*Cc];      // rowsum  (mean over axis1): S1[b,t,c] = (1/n) sum_i x[b,i,t,c]
__device__ float g_S2[Bn*Nn*Cc];      // colsum  (mean over axis2): S2[b,t,c] = (1/n) sum_j x[b,t,j,c]
__device__ float g_D [Bn*Nn*Cc];      // diag:   D[b,t,c] = x[b,t,t,c]
__device__ float g_p [Bn*Nn*Mm];      // sigmoid neighborhood
__device__ float g_U [Bn*Nn*Mm*Cc];   // U[b,t,m,c] = (1/n) sum_i p[i,m] x[b,i,t,c]
__device__ float g_V [Bn*Nn*Mm*Cc];   // V[b,t,m,c] = (1/n) sum_j p[j,m] x[b,t,j,c]
__device__ float g_part1[Bn*8*128];   // rcs2 partials (8 t-slices per b)
__device__ float g_part2[Bn*8*128];   // ds2  partials
__device__ float g_add[Bn*Nn*OUTn];   // per (b, j, o) additive term
__device__ __half g_Wt[OUTn*2*Mm*Cc]; // w2d transposed: Wt[o][k], k = 0..255

// ---------------- sweep 1: rowpass (S2, D) + colpass (S1) + w2d->half, one launch ----------------
__global__ void k_sweep1(const float* __restrict__ x, const float* __restrict__ w2d){
    int blk = blockIdx.x;
    int tid = threadIdx.x;
    if (blk >= 2*Bn*Nn){
        int idx = (blk - 2*Bn*Nn) * 256 + tid;   // 16384
        int o = idx >> 8, k = idx & 255;
        g_Wt[idx] = __float2half(w2d[k*OUTn + o]);
        return;
    }
    __shared__ float red[8][32];
    int c = tid & 31, g = tid >> 5;
    if (blk < Bn*Nn){
        int bt = blk;
        int t = bt & (Nn-1);
        const float* xrow = x + (size_t)bt * Nn * Cc;
        float s = 0.f;
        #pragma unroll 8
        for (int j = g; j < Nn; j += 8) s += xrow[j*Cc + c];
        red[g][c] = s;
        __syncthreads();
        if (g == 0){
            float tot = 0.f;
            #pragma unroll
            for (int k = 0; k < 8; k++) tot += red[k][c];
            g_S2[bt*Cc + c] = tot * (1.0f/Nn);
            g_D [bt*Cc + c] = xrow[t*Cc + c];
        }
    } else {
        int bt = blk - Bn*Nn;
        int b = bt >> 8, t = bt & (Nn-1);
        const float* xb = x + (size_t)b*Nn*Nn*Cc + (size_t)t*Cc;
        float s = 0.f;
        #pragma unroll 8
        for (int i = g; i < Nn; i += 8) s += xb[(size_t)i*Nn*Cc + c];
        red[g][c] = s;
        __syncthreads();
        if (g == 0){
            float tot = 0.f;
            #pragma unroll
            for (int k = 0; k < 8; k++) tot += red[k][c];
            g_S1[bt*Cc + c] = tot * (1.0f/Nn);
        }
    }
}

// ---------------- neighborhood sigmoid: p[b,t,m], 1024 threads ----------------
__global__ __launch_bounds__(1024) void k_neighb(const float* __restrict__ w1, const float* __restrict__ b1,
                         const float* __restrict__ w0, const float* __restrict__ b0){
    int b = blockIdx.x;
    __shared__ float w1s[3*Cc*Mm];   // 384
    __shared__ float w0s[2*Cc*Mm];   // 256
    __shared__ float rcs[Cc], ds[Cc], z0[Mm];
    __shared__ float r1[32][32], r2[32][32];
    int tid = threadIdx.x;
    if (tid < 3*Cc*Mm) w1s[tid] = w1[tid];
    if (tid < 2*Cc*Mm) w0s[tid] = w0[tid];
    int c = tid & 31, g = tid >> 5;     // 32 groups
    float s1 = 0.f, s2 = 0.f;
    #pragma unroll
    for (int t = g; t < Nn; t += 32){
        s1 += g_S1[(b*Nn + t)*Cc + c];
        s2 += g_D [(b*Nn + t)*Cc + c];
    }
    r1[g][c] = s1; r2[g][c] = s2;
    __syncthreads();
    if (tid < 32){
        float a = 0.f, d = 0.f;
        #pragma unroll
        for (int k = 0; k < 32; k++){ a += r1[k][c]; d += r2[k][c]; }
        rcs[c] = a * (1.0f/Nn);
        ds[c]  = d * (1.0f/Nn);
    }
    __syncthreads();
    if (tid < Mm){
        int m = tid;
        float z = b0[m];
        #pragma unroll
        for (int cc = 0; cc < Cc; cc++)
            z += rcs[cc]*w0s[cc*Mm + m] + ds[cc]*w0s[(Cc+cc)*Mm + m];
        z0[m] = z;
    }
    __syncthreads();
    // one thread per (t, m)
    int t = tid >> 2, m = tid & 3;
    const float* S1r = &g_S1[(b*Nn + t)*Cc];
    const float* S2r = &g_S2[(b*Nn + t)*Cc];
    const float* Dr  = &g_D [(b*Nn + t)*Cc];
    float node = b1[m] + z0[m];
    #pragma unroll
    for (int cc = 0; cc < Cc; cc++)
        node += S1r[cc]*w1s[cc*Mm+m] + S2r[cc]*w1s[(Cc+cc)*Mm+m] + Dr[cc]*w1s[(2*Cc+cc)*Mm+m];
    g_p[(b*Nn + t)*Mm + m] = 1.0f / (1.0f + expf(-node));
}

// ---------------- sweep 2: p-weighted contractions (V and U) in one launch ----------------
__global__ void k_sweep2(const float* __restrict__ x){
    int blk = blockIdx.x;
    bool is_v = blk < Bn*Nn;
    int bt = is_v ? blk : blk - Bn*Nn;
    int b = bt >> 8, t = bt & (Nn-1);
    const float* base;
    size_t stride;
    if (is_v){ base = x + (size_t)bt * Nn * Cc;                     stride = Cc; }
    else     { base = x + (size_t)b*Nn*Nn*Cc + (size_t)t*Cc;        stride = (size_t)Nn*Cc; }
    __shared__ float pv[Nn*Mm];
    __shared__ float red[8*Mm*32];
    int tid = threadIdx.x;
    for (int idx = tid; idx < Nn*Mm; idx += 256) pv[idx] = g_p[b*Nn*Mm + idx];
    __syncthreads();
    int c = tid & 31, g = tid >> 5;
    float acc[Mm] = {0.f,0.f,0.f,0.f};
    #pragma unroll 8
    for (int j = g; j < Nn; j += 8){
        float v = base[(size_t)j*stride + c];
        #pragma unroll
        for (int m = 0; m < Mm; m++) acc[m] += v * pv[j*Mm + m];
    }
    #pragma unroll
    for (int m = 0; m < Mm; m++) red[(g*Mm + m)*32 + c] = acc[m];
    __syncthreads();
    if (g < Mm){
        int m = g;
        float s = 0.f;
        #pragma unroll
        for (int k = 0; k < 8; k++) s += red[(k*Mm + m)*32 + c];
        float* dst = is_v ? g_V : g_U;
        dst[(bt*Mm + m)*Cc + c] = s * (1.0f/Nn);
    }
}

// ---------------- rcs2/ds2 partials: grid = Bn*8, 16 t per thread ----------------
__global__ void k_rcs2p(){
    int blk = blockIdx.x;
    int b = blk >> 3, slice = blk & 7;
    __shared__ float pr1[256], pr2[256];
    int tid = threadIdx.x;
    int mc = tid & 127, sub = tid >> 7;
    int m = mc >> 5, c = mc & 31;
    float s1 = 0.f, s2 = 0.f;
    int t0 = slice*32 + sub*16;
    #pragma unroll
    for (int t = t0; t < t0+16; t++){
        float pvv = g_p[(b*Nn + t)*Mm + m];
        s1 += pvv * g_V[((b*Nn + t)*Mm + m)*Cc + c];
        s2 += pvv * pvv * g_D[(b*Nn + t)*Cc + c];
    }
    pr1[tid] = s1; pr2[tid] = s2;
    __syncthreads();
    if (tid < 128){
        g_part1[(b*8 + slice)*128 + tid] = pr1[tid] + pr1[tid+128];
        g_part2[(b*8 + slice)*128 + tid] = pr2[tid] + pr2[tid+128];
    }
}

// add[b,t,o] = obj1d[b,t,:] @ w1d[:,o] + z0[b,o]; z0 computed in prologue from partials
#define ADD_SMEM (16*384*4 + 192*64*4)
__global__ void k_add(const float* __restrict__ w1d, const float* __restrict__ w0d,
                      const float* __restrict__ b0d, const float* __restrict__ b1d,
                      const float* __restrict__ b2d){
    extern __shared__ float ash[];
    float* o1  = ash;            // [16][384]
    float* wsh = ash + 16*384;   // [192][64]
    __shared__ float rsh[128], dsh[128], zred[256], z0sh[64];
    int b = blockIdx.x >> 4;
    int t0 = (blockIdx.x & 15) * 16;
    int tid = threadIdx.x;

    // fill o1
    for (int idx = tid; idx < 16*384; idx += 256){
        int tl = idx / 384, k = idx - tl*384;
        int t = t0 + tl;
        int seg = k >> 7, mc = k & 127;
        int m = mc >> 5, c = mc & 31;
        float pv = g_p[(b*Nn + t)*Mm + m];
        float val;
        if (seg == 0)      val = pv * g_U[((b*Nn + t)*Mm + m)*Cc + c];
        else if (seg == 1) val = pv * g_V[((b*Nn + t)*Mm + m)*Cc + c];
        else               val = pv * pv * g_D[(b*Nn + t)*Cc + c];
        o1[tl*384 + k] = val;
    }
    // prologue: reduce rcs2/ds2 partials
    if (tid < 128){
        float a = 0.f, d = 0.f;
        #pragma unroll
        for (int s = 0; s < 8; s++){
            a += g_part1[(b*8 + s)*128 + tid];
            d += g_part2[(b*8 + s)*128 + tid];
        }
        rsh[tid] = a * (1.0f/Nn);
        dsh[tid] = d * (1.0f/Nn);
    }
    __syncthreads();
    // z0[o] = sum_k rsh[k]w0d[k][o] + dsh[k]w0d[128+k][o], 4-way k split
    {
        int o = tid & 63, q = tid >> 6;
        float s = 0.f;
        int k0 = q*32;
        #pragma unroll
        for (int k = k0; k < k0+32; k++)
            s += rsh[k]*w0d[k*OUTn + o] + dsh[k]*w0d[(128+k)*OUTn + o];
        zred[tid] = s;
    }
    __syncthreads();
    if (tid < 64)
        z0sh[tid] = zred[tid] + zred[tid+64] + zred[tid+128] + zred[tid+192]
                  + b0d[tid] + b1d[tid] + b2d[tid];

    int tl4 = tid >> 6, o = tid & 63;
    float acc[4] = {0.f,0.f,0.f,0.f};
    #pragma unroll
    for (int chunk = 0; chunk < 2; chunk++){
        __syncthreads();
        {   // vectorized w1d chunk load: 192*64 floats = 3072 float4
            const float4* w4 = (const float4*)(w1d + chunk*192*64);
            #pragma unroll
            for (int it = 0; it < 12; it++)
                ((float4*)wsh)[tid + it*256] = w4[tid + it*256];
        }
        __syncthreads();
        #pragma unroll 8
        for (int k = 0; k < 192; k++){
            float wv = wsh[k*64 + o];
            #pragma unroll
            for (int q = 0; q < 4; q++)
                acc[q] += o1[(tl4*4 + q)*384 + chunk*192 + k] * wv;
        }
    }
    float z = z0sh[o];
    #pragma unroll
    for (int q = 0; q < 4; q++)
        g_add[(b*Nn + t0 + tl4*4 + q)*OUTn + o] = acc[q] + z;
}

// ---------------- main fused GEMM (JPB j per block: W tile reused) ----------------
__device__ __forceinline__ void mma16816(float* c, const uint32_t* a, uint32_t b0, uint32_t b1){
    asm volatile("mma.sync.aligned.m16n8k16.row.col.f32.f16.f16.f32 "
        "{%0,%1,%2,%3}, {%4,%5,%6,%7}, {%8,%9}, {%0,%1,%2,%3};\n"
        : "+f"(c[0]), "+f"(c[1]), "+f"(c[2]), "+f"(c[3])
        : "r"(a[0]), "r"(a[1]), "r"(a[2]), "r"(a[3]), "r"(b0), "r"(b1));
}

#define AS 264   // padded row stride (halves) for A and W tiles
#define SMEM_MAIN (128*AS*2 + 64*AS*2 + 512*4 + 64*4)
#define JPB 4

__global__ __launch_bounds__(256, 2) void k_main(const float* __restrict__ x, float* __restrict__ out){
    extern __shared__ __align__(16) char smem[];
    __half* Ash  = (__half*)smem;                 // [128][AS]
    __half* Wsh  = Ash + 128*AS;                  // [64][AS]
    float*  sshf = (float*)(Wsh + 64*AS);         // [128][4] s_m factors
    float*  addsh = sshf + 512;                   // [64]

    int blk = blockIdx.x;
    int ib = blk & 1, jp = (blk >> 1) & 63, b = blk >> 7;
    int i0 = ib * 128;
    int tid = threadIdx.x;

    // W tile: 64 rows x 256 halves = 2048 uint4, loaded once for JPB j's
    {
        const uint4* Wt4 = (const uint4*)g_Wt;
        #pragma unroll
        for (int it = 0; it < 8; it++){
            int idx = tid + it*256;               // < 2048
            int o = idx >> 5, kq = idx & 31;
            *(uint4*)&Wsh[o*AS + kq*8] = Wt4[idx];
        }
    }

    float4 pi4;
    if (tid < 128) pi4 = ((const float4*)g_p)[b*Nn + i0 + tid];

    int lane = tid & 31, wid = tid >> 5;
    int wr = wid >> 1, wc = wid & 1;              // 4 row-tiles x 2 col-tiles of warps
    int gid = lane >> 2, tg = lane & 3;

    #pragma unroll
    for (int jj = 0; jj < JPB; jj++){
        int j = jp*JPB + jj;
        if (jj > 0) __syncthreads();              // protect Ash/sshf rewrite

        if (tid < 128){
            float4 pj = ((const float4*)g_p)[b*Nn + j];
            ((float4*)sshf)[tid] = make_float4(pi4.x*pj.x, pi4.y*pj.y, pi4.z*pj.z, pi4.w*pj.w);
        }
        if (tid < 64) addsh[tid] = g_add[(b*Nn + j)*OUTn + tid];
        __syncthreads();

        // build A tile: A[i][m*32+c] = s_m * x[b,i0+i,j,c];  A[i][128+m*32+c] = s_m * x[b,j,i0+i,c]
        {
            size_t base_c = (((size_t)(b*Nn) + i0)*Nn + j)*Cc;
            size_t base_r = (((size_t)(b*Nn) + j)*Nn + i0)*Cc;
            #pragma unroll
            for (int it = 0; it < 8; it++){
                int idx = tid + it*256;               // < 2048
                int i = idx >> 4, cp = idx & 15;
                float2 v = *(const float2*)(x + base_c + (size_t)i*(Nn*Cc) + cp*2);
                float4 s = ((const float4*)sshf)[i];
                __half* arow = Ash + i*AS + cp*2;
                *(half2*)(arow     ) = __floats2half2_rn(s.x*v.x, s.x*v.y);
                *(half2*)(arow + 32) = __floats2half2_rn(s.y*v.x, s.y*v.y);
                *(half2*)(arow + 64) = __floats2half2_rn(s.z*v.x, s.z*v.y);
                *(half2*)(arow + 96) = __floats2half2_rn(s.w*v.x, s.w*v.y);
            }
            #pragma unroll
            for (int it = 0; it < 8; it++){
                int idx = tid + it*256;
                int i = idx >> 4, cp = idx & 15;
                float2 v = *(const float2*)(x + base_r + (size_t)i*Cc + cp*2);
                float4 s = ((const float4*)sshf)[i];
                __half* arow = Ash + i*AS + 128 + cp*2;
                *(half2*)(arow     ) = __floats2half2_rn(s.x*v.x, s.x*v.y);
                *(half2*)(arow + 32) = __floats2half2_rn(s.y*v.x, s.y*v.y);
                *(half2*)(arow + 64) = __floats2half2_rn(s.z*v.x, s.z*v.y);
                *(half2*)(arow + 96) = __floats2half2_rn(s.w*v.x, s.w*v.y);
            }
        }
        __syncthreads();

        float acc[2][4][4];
        #pragma unroll
        for (int rt = 0; rt < 2; rt++)
            #pragma unroll
            for (int nt = 0; nt < 4; nt++)
                #pragma unroll
                for (int q = 0; q < 4; q++) acc[rt][nt][q] = 0.f;

        #pragma unroll
        for (int kk = 0; kk < 16; kk++){
            int k0 = kk*16;
            uint32_t a[2][4];
            #pragma unroll
            for (int rt = 0; rt < 2; rt++){
                int r = wr*32 + rt*16 + gid;
                const __half* ap = Ash + r*AS + k0 + tg*2;
                a[rt][0] = *(const uint32_t*)(ap);
                a[rt][1] = *(const uint32_t*)(ap + 8*AS);
                a[rt][2] = *(const uint32_t*)(ap + 8);
                a[rt][3] = *(const uint32_t*)(ap + 8*AS + 8);
            }
            #pragma unroll
            for (int nt = 0; nt < 4; nt++){
                int o = wc*32 + nt*8 + gid;
                const __half* bp = Wsh + o*AS + k0 + tg*2;
                uint32_t b0 = *(const uint32_t*)(bp);
                uint32_t b1 = *(const uint32_t*)(bp + 8);
                mma16816(acc[0][nt], a[0], b0, b1);
                mma16816(acc[1][nt], a[1], b0, b1);
            }
        }

        #pragma unroll
        for (int rt = 0; rt < 2; rt++){
            int r = i0 + wr*32 + rt*16 + gid;
            #pragma unroll
            for (int nt = 0; nt < 4; nt++){
                int o = wc*32 + nt*8 + tg*2;
                float2 ad = *(const float2*)&addsh[o];
                size_t base = (((size_t)(b*Nn) + r)*Nn + j)*OUTn + o;
                float2 v0 = make_float2(acc[rt][nt][0] + ad.x, acc[rt][nt][1] + ad.y);
                float2 v1 = make_float2(acc[rt][nt][2] + ad.x, acc[rt][nt][3] + ad.y);
                *(float2*)(out + base) = v0;
                *(float2*)(out + base + (size_t)8*Nn*OUTn) = v1;
            }
        }
    }
}

// ---------------- launch ----------------
extern "C" void kernel_launch(void* const* d_in, const int* in_sizes, int n_in,
                              void* d_out, int out_size) {
    const float* x    = (const float*)d_in[0];
    const float* w1nb = (const float*)d_in[1];
    const float* b1nb = (const float*)d_in[2];
    const float* w0nb = (const float*)d_in[3];
    const float* b0nb = (const float*)d_in[4];
    const float* w2d  = (const float*)d_in[5];
    const float* b2d  = (const float*)d_in[6];
    const float* w1d  = (const float*)d_in[7];
    const float* b1d  = (const float*)d_in[8];
    const float* w0d  = (const float*)d_in[9];
    const float* b0d  = (const float*)d_in[10];
    float* out = (float*)d_out;

    cudaFuncSetAttribute(k_main, cudaFuncAttributeMaxDynamicSharedMemorySize, SMEM_MAIN);
    cudaFuncSetAttribute(k_add, cudaFuncAttributeMaxDynamicSharedMemorySize, ADD_SMEM);

    k_sweep1<<<2*Bn*Nn + 64, 256>>>(x, w2d);
    k_neighb<<<Bn, 1024>>>(w1nb, b1nb, w0nb, b0nb);
    k_sweep2<<<2*Bn*Nn, 256>>>(x);
    k_rcs2p<<<Bn*8, 256>>>();
    k_add<<<Bn*16, 256, ADD_SMEM>>>(w1d, w0d, b0d, b1d, b2d);
    k_main<<<Bn*Nn*2/JPB, 256, SMEM_MAIN>>>(x, out);
}